// round 1
// baseline (speedup 1.0000x reference)
#include <cuda_runtime.h>
#include <cstdint>

// MoE FFN: T=8192 tokens, H=1024, I=2816, E=8 experts (top-2) + shared expert.
// Strategy: fp32 router + expert gather, then tf32 mma.sync GEMMs:
//   GEMM1 (fused gate+up, SiLU*up epilogue) -> Abuf
//   GEMM2 (down proj; shared -> out, routed -> weighted slot buffer)
//   combine: out += slot0 + slot1   (deterministic, no float atomics)

#define T_TOKENS 8192
#define H_DIM    1024
#define I_DIM    2816
#define NEXP     8
#define SEGS     9          // 8 routed experts + 1 shared

// ---------------- static device scratch (allocation-free rule) ----------------
__device__ float g_Abuf[(size_t)SEGS * T_TOKENS * I_DIM];   // SwiGLU intermediate
__device__ float g_Dbuf[(size_t)2 * T_TOKENS * H_DIM];      // weighted routed down-proj per slot
__device__ int   g_tok [NEXP * T_TOKENS];
__device__ float g_wgt [NEXP * T_TOKENS];
__device__ int   g_slot[NEXP * T_TOKENS];
__device__ int   g_cnt [NEXP];

// ---------------- helpers ----------------
__device__ __forceinline__ float cvt_tf32(float f) {
    uint32_t u;
    asm("cvt.rna.tf32.f32 %0, %1;" : "=r"(u) : "f"(f));
    return __uint_as_float(u);
}

__device__ __forceinline__ void mma_tf32(float (&d)[4], const uint32_t (&a)[4],
                                         const uint32_t (&b)[2]) {
    asm volatile(
        "mma.sync.aligned.m16n8k8.row.col.f32.tf32.tf32.f32 "
        "{%0,%1,%2,%3}, {%4,%5,%6,%7}, {%8,%9}, {%0,%1,%2,%3};\n"
        : "+f"(d[0]), "+f"(d[1]), "+f"(d[2]), "+f"(d[3])
        : "r"(a[0]), "r"(a[1]), "r"(a[2]), "r"(a[3]), "r"(b[0]), "r"(b[1]));
}

// ---------------- kernel 0: zero expert counters ----------------
__global__ void zero_cnt_kernel() {
    if (threadIdx.x < NEXP) g_cnt[threadIdx.x] = 0;
}

// ---------------- kernel 1: fp32 router (softmax -> top2 -> renorm -> scatter) ----------------
__global__ void router_kernel(const float* __restrict__ x, const float* __restrict__ gw) {
    __shared__ float sx[H_DIM];
    __shared__ float slog[NEXP];
    const int t = blockIdx.x;
    for (int i = threadIdx.x; i < H_DIM; i += 256) sx[i] = x[(size_t)t * H_DIM + i];
    __syncthreads();
    const int wid = threadIdx.x >> 5, lane = threadIdx.x & 31;
    // 8 warps -> 8 experts
    float s = 0.f;
    const float* w = gw + wid * H_DIM;
    for (int k = lane; k < H_DIM; k += 32) s += sx[k] * w[k];
#pragma unroll
    for (int o = 16; o; o >>= 1) s += __shfl_xor_sync(0xffffffffu, s, o);
    if (lane == 0) slog[wid] = s;
    __syncthreads();
    if (threadIdx.x == 0) {
        float p[NEXP];
        float mx = slog[0];
#pragma unroll
        for (int e = 1; e < NEXP; e++) mx = fmaxf(mx, slog[e]);
        float sum = 0.f;
#pragma unroll
        for (int e = 0; e < NEXP; e++) { p[e] = expf(slog[e] - mx); sum += p[e]; }
        const float inv = 1.f / sum;
#pragma unroll
        for (int e = 0; e < NEXP; e++) p[e] *= inv;
        // top-2, ties -> lowest index (matches jax.lax.top_k)
        int i0 = 0;
#pragma unroll
        for (int e = 1; e < NEXP; e++) if (p[e] > p[i0]) i0 = e;
        int i1 = (i0 == 0) ? 1 : 0;
#pragma unroll
        for (int e = 0; e < NEXP; e++) if (e != i1 && e != i0 && p[e] > p[i1]) i1 = e;
        float w0 = p[i0], w1 = p[i1];
        const float rn = 1.f / (w0 + w1 + 1e-20f);
        w0 *= rn; w1 *= rn;
        int p0 = atomicAdd(&g_cnt[i0], 1);
        g_tok [i0 * T_TOKENS + p0] = t;
        g_wgt [i0 * T_TOKENS + p0] = w0;
        g_slot[i0 * T_TOKENS + p0] = 2 * t;
        int p1 = atomicAdd(&g_cnt[i1], 1);
        g_tok [i1 * T_TOKENS + p1] = t;
        g_wgt [i1 * T_TOKENS + p1] = w1;
        g_slot[i1 * T_TOKENS + p1] = 2 * t + 1;
    }
}

// ---------------- kernel 2: fused gate+up GEMM (tf32 mma) + SiLU*up epilogue ----------------
// C[rows, I] over gathered token rows; tile BM=128, BN=64 (x2 matrices), BK=32.
__global__ __launch_bounds__(256, 2) void gemm1_kernel(
    const float* __restrict__ x,
    const float* __restrict__ eg, const float* __restrict__ eu,
    const float* __restrict__ sg, const float* __restrict__ su) {
    const int seg = blockIdx.x >> 6;
    const int mt  = blockIdx.x & 63;
    const int nt  = blockIdx.y;
    const float *wg, *wu;
    if (seg < NEXP) {
        if (mt * 128 >= g_cnt[seg]) return;
        wg = eg + (size_t)seg * I_DIM * H_DIM;
        wu = eu + (size_t)seg * I_DIM * H_DIM;
    } else { wg = sg; wu = su; }

    __shared__ float sX[128][36];   // pad 4 -> stride 36 floats (conflict-free frag loads)
    __shared__ float sG[64][36];
    __shared__ float sU[64][36];

    const int tid = threadIdx.x;
    const int wid = tid >> 5, lane = tid & 31;
    const int wm = (wid >> 1) * 32, wn = (wid & 1) * 32;
    const int m0 = mt * 128, n0 = nt * 64;
    const int lr = tid >> 3, lc = (tid & 7) * 4;

    float accg[2][4][4] = {};
    float accu[2][4][4] = {};

    for (int kk = 0; kk < H_DIM; kk += 32) {
#pragma unroll
        for (int p = 0; p < 4; p++) {
            const int r = p * 32 + lr;
            const int token = (seg == NEXP) ? (m0 + r) : g_tok[seg * T_TOKENS + m0 + r];
            const float4 v = *(const float4*)(x + (size_t)token * H_DIM + kk + lc);
            *(float4*)&sX[r][lc] =
                make_float4(cvt_tf32(v.x), cvt_tf32(v.y), cvt_tf32(v.z), cvt_tf32(v.w));
        }
#pragma unroll
        for (int p = 0; p < 2; p++) {
            const int r = p * 32 + lr;
            const float4 vg = *(const float4*)(wg + (size_t)(n0 + r) * H_DIM + kk + lc);
            const float4 vu = *(const float4*)(wu + (size_t)(n0 + r) * H_DIM + kk + lc);
            *(float4*)&sG[r][lc] =
                make_float4(cvt_tf32(vg.x), cvt_tf32(vg.y), cvt_tf32(vg.z), cvt_tf32(vg.w));
            *(float4*)&sU[r][lc] =
                make_float4(cvt_tf32(vu.x), cvt_tf32(vu.y), cvt_tf32(vu.z), cvt_tf32(vu.w));
        }
        __syncthreads();
        const int rr = lane >> 2, cc = lane & 3;
#pragma unroll
        for (int ka = 0; ka < 32; ka += 8) {
            uint32_t a[2][4];
#pragma unroll
            for (int i = 0; i < 2; i++) {
                a[i][0] = __float_as_uint(sX[wm + i * 16 + rr    ][ka + cc    ]);
                a[i][1] = __float_as_uint(sX[wm + i * 16 + rr + 8][ka + cc    ]);
                a[i][2] = __float_as_uint(sX[wm + i * 16 + rr    ][ka + cc + 4]);
                a[i][3] = __float_as_uint(sX[wm + i * 16 + rr + 8][ka + cc + 4]);
            }
#pragma unroll
            for (int j = 0; j < 4; j++) {
                uint32_t bg[2], bu2[2];
                bg [0] = __float_as_uint(sG[wn + j * 8 + rr][ka + cc    ]);
                bg [1] = __float_as_uint(sG[wn + j * 8 + rr][ka + cc + 4]);
                bu2[0] = __float_as_uint(sU[wn + j * 8 + rr][ka + cc    ]);
                bu2[1] = __float_as_uint(sU[wn + j * 8 + rr][ka + cc + 4]);
#pragma unroll
                for (int i = 0; i < 2; i++) {
                    mma_tf32(accg[i][j], a[i], bg);
                    mma_tf32(accu[i][j], a[i], bu2);
                }
            }
        }
        __syncthreads();
    }
    // epilogue: A = silu(g) * u
    const int rr = lane >> 2, cc2 = (lane & 3) * 2;
#pragma unroll
    for (int i = 0; i < 2; i++)
#pragma unroll
        for (int j = 0; j < 4; j++)
#pragma unroll
            for (int q = 0; q < 2; q++) {
                const int row = m0 + wm + i * 16 + rr + q * 8;
                const int col = n0 + wn + j * 8 + cc2;
                const float g0 = accg[i][j][q * 2 + 0], g1 = accg[i][j][q * 2 + 1];
                const float u0 = accu[i][j][q * 2 + 0], u1 = accu[i][j][q * 2 + 1];
                const float a0 = g0 / (1.f + __expf(-g0)) * u0;
                const float a1 = g1 / (1.f + __expf(-g1)) * u1;
                *(float2*)&g_Abuf[((size_t)seg * T_TOKENS + row) * I_DIM + col] =
                    make_float2(a0, a1);
            }
}

// ---------------- kernel 3: down GEMM (tf32 mma) ----------------
// BM=128, BN=128, BK=32. shared seg -> out directly; routed -> weighted slot buffer.
__global__ __launch_bounds__(256, 2) void gemm2_kernel(
    const float* __restrict__ ed, const float* __restrict__ sd, float* __restrict__ out) {
    const int seg = blockIdx.x >> 6;
    const int mt  = blockIdx.x & 63;
    const int nt  = blockIdx.y;
    int cnt = T_TOKENS;
    const float* wd;
    if (seg < NEXP) {
        cnt = g_cnt[seg];
        if (mt * 128 >= cnt) return;
        wd = ed + (size_t)seg * H_DIM * I_DIM;
    } else wd = sd;

    __shared__ float sA[128][36];
    __shared__ float sW[128][36];
    const int tid = threadIdx.x, wid = tid >> 5, lane = tid & 31;
    const int wm = (wid >> 2) * 64, wn = (wid & 3) * 32;
    const int m0 = mt * 128, n0 = nt * 128;
    const int lr = tid >> 3, lc = (tid & 7) * 4;
    const float* Arows = g_Abuf + (size_t)seg * T_TOKENS * I_DIM;

    float acc[4][4][4] = {};
    for (int kk = 0; kk < I_DIM; kk += 32) {
#pragma unroll
        for (int p = 0; p < 4; p++) {
            const int r = p * 32 + lr;
            const float4 v = *(const float4*)(Arows + (size_t)(m0 + r) * I_DIM + kk + lc);
            *(float4*)&sA[r][lc] =
                make_float4(cvt_tf32(v.x), cvt_tf32(v.y), cvt_tf32(v.z), cvt_tf32(v.w));
            const float4 w = *(const float4*)(wd + (size_t)(n0 + r) * I_DIM + kk + lc);
            *(float4*)&sW[r][lc] =
                make_float4(cvt_tf32(w.x), cvt_tf32(w.y), cvt_tf32(w.z), cvt_tf32(w.w));
        }
        __syncthreads();
        const int rr = lane >> 2, cc = lane & 3;
#pragma unroll
        for (int ka = 0; ka < 32; ka += 8) {
            uint32_t a[4][4], b[4][2];
#pragma unroll
            for (int i = 0; i < 4; i++) {
                a[i][0] = __float_as_uint(sA[wm + i * 16 + rr    ][ka + cc    ]);
                a[i][1] = __float_as_uint(sA[wm + i * 16 + rr + 8][ka + cc    ]);
                a[i][2] = __float_as_uint(sA[wm + i * 16 + rr    ][ka + cc + 4]);
                a[i][3] = __float_as_uint(sA[wm + i * 16 + rr + 8][ka + cc + 4]);
            }
#pragma unroll
            for (int j = 0; j < 4; j++) {
                b[j][0] = __float_as_uint(sW[wn + j * 8 + rr][ka + cc    ]);
                b[j][1] = __float_as_uint(sW[wn + j * 8 + rr][ka + cc + 4]);
            }
#pragma unroll
            for (int i = 0; i < 4; i++)
#pragma unroll
                for (int j = 0; j < 4; j++) mma_tf32(acc[i][j], a[i], b[j]);
        }
        __syncthreads();
    }
    const int rr = lane >> 2, cc2 = (lane & 3) * 2;
#pragma unroll
    for (int i = 0; i < 4; i++)
#pragma unroll
        for (int j = 0; j < 4; j++)
#pragma unroll
            for (int q = 0; q < 2; q++) {
                const int row = m0 + wm + i * 16 + rr + q * 8;   // row within segment
                const int col = n0 + wn + j * 8 + cc2;
                const float v0 = acc[i][j][q * 2 + 0], v1 = acc[i][j][q * 2 + 1];
                if (seg == NEXP) {
                    *(float2*)&out[(size_t)row * H_DIM + col] = make_float2(v0, v1);
                } else if (row < cnt) {
                    const int idx  = seg * T_TOKENS + row;
                    const float w  = g_wgt[idx];
                    const int slot = g_slot[idx];
                    *(float2*)&g_Dbuf[(size_t)slot * H_DIM + col] =
                        make_float2(w * v0, w * v1);
                }
            }
}

// ---------------- kernel 4: combine shared + 2 routed slots ----------------
__global__ void combine_kernel(float* __restrict__ out) {
    const size_t i = (size_t)blockIdx.x * 256 + threadIdx.x;
    const int t = (int)(i >> 10), h = (int)(i & 1023);
    out[i] += g_Dbuf[(size_t)(2 * t) * H_DIM + h] + g_Dbuf[(size_t)(2 * t + 1) * H_DIM + h];
}

// ---------------- launch ----------------
extern "C" void kernel_launch(void* const* d_in, const int* in_sizes, int n_in,
                              void* d_out, int out_size) {
    const float* x  = (const float*)d_in[0];
    const float* gw = (const float*)d_in[1];
    const float* eg = (const float*)d_in[2];
    const float* eu = (const float*)d_in[3];
    const float* ed = (const float*)d_in[4];
    const float* sg = (const float*)d_in[5];
    const float* su = (const float*)d_in[6];
    const float* sd = (const float*)d_in[7];
    float* out = (float*)d_out;

    zero_cnt_kernel<<<1, 32>>>();
    router_kernel<<<T_TOKENS, 256>>>(x, gw);
    gemm1_kernel<<<dim3(SEGS * 64, I_DIM / 64), 256>>>(x, eg, eu, sg, su);
    gemm2_kernel<<<dim3(SEGS * 64, H_DIM / 128), 256>>>(ed, sd, out);
    combine_kernel<<<(T_TOKENS * H_DIM) / 256, 256>>>(out);
}

// round 3
// speedup vs baseline: 1.2618x; 1.2618x over previous
#include <cuda_runtime.h>
#include <cstdint>

// MoE FFN: T=8192 tokens, H=1024, I=2816, E=8 experts (top-2) + shared expert.
// R3 (= R2 resubmit; broker timeout last round): pre-convert weights/x to
// tf32-rounded fp32, cp.async 2-stage pipeline, ldmatrix fragment loads.
// Numerics identical to R1 passing kernel (same RN tf32 rounding points).

#define T_TOKENS 8192
#define H_DIM    1024
#define I_DIM    2816
#define NEXP     8
#define SEGS     9

// ---------------- static device scratch ----------------
__device__ float g_Abuf[(size_t)SEGS * T_TOKENS * I_DIM];
__device__ float g_Dbuf[(size_t)2 * T_TOKENS * H_DIM];
__device__ int   g_tok [NEXP * T_TOKENS];
__device__ float g_wgt [NEXP * T_TOKENS];
__device__ int   g_slot[NEXP * T_TOKENS];
__device__ int   g_cnt [NEXP];
// tf32-rounded copies (enables raw cp.async in the GEMMs)
__device__ float g_xc [(size_t)T_TOKENS * H_DIM];
__device__ float g_egc[(size_t)NEXP * I_DIM * H_DIM];
__device__ float g_euc[(size_t)NEXP * I_DIM * H_DIM];
__device__ float g_edc[(size_t)NEXP * H_DIM * I_DIM];
__device__ float g_sgc[(size_t)I_DIM * H_DIM];
__device__ float g_suc[(size_t)I_DIM * H_DIM];
__device__ float g_sdc[(size_t)H_DIM * I_DIM];

// ---------------- helpers ----------------
__device__ __forceinline__ float cvt_tf32(float f) {
    uint32_t u;
    asm("cvt.rna.tf32.f32 %0, %1;" : "=r"(u) : "f"(f));
    return __uint_as_float(u);
}

__device__ __forceinline__ void mma_tf32(float (&d)[4], const uint32_t (&a)[4],
                                         const uint32_t (&b)[2]) {
    asm volatile(
        "mma.sync.aligned.m16n8k8.row.col.f32.tf32.tf32.f32 "
        "{%0,%1,%2,%3}, {%4,%5,%6,%7}, {%8,%9}, {%0,%1,%2,%3};\n"
        : "+f"(d[0]), "+f"(d[1]), "+f"(d[2]), "+f"(d[3])
        : "r"(a[0]), "r"(a[1]), "r"(a[2]), "r"(a[3]), "r"(b[0]), "r"(b[1]));
}

__device__ __forceinline__ void ldsm4(uint32_t& r0, uint32_t& r1, uint32_t& r2,
                                      uint32_t& r3, uint32_t addr) {
    asm volatile("ldmatrix.sync.aligned.m8n8.x4.shared.b16 {%0,%1,%2,%3}, [%4];\n"
                 : "=r"(r0), "=r"(r1), "=r"(r2), "=r"(r3) : "r"(addr));
}

__device__ __forceinline__ void cp16(float* dst, const float* src) {
    uint32_t d = (uint32_t)__cvta_generic_to_shared(dst);
    asm volatile("cp.async.cg.shared.global [%0], [%1], 16;\n" :: "r"(d), "l"(src));
}
__device__ __forceinline__ void cp_commit() {
    asm volatile("cp.async.commit_group;\n");
}
template <int N>
__device__ __forceinline__ void cp_wait() {
    asm volatile("cp.async.wait_group %0;\n" :: "n"(N));
}

// ---------------- kernel: tf32 pre-round (which selects dst) ----------------
__global__ void cvt_kernel(const float* __restrict__ src, int which, size_t n4) {
    float* dst;
    switch (which) {
        case 0: dst = g_xc;  break;
        case 1: dst = g_egc; break;
        case 2: dst = g_euc; break;
        case 3: dst = g_edc; break;
        case 4: dst = g_sgc; break;
        case 5: dst = g_suc; break;
        default: dst = g_sdc; break;
    }
    size_t i = (size_t)blockIdx.x * blockDim.x + threadIdx.x;
    const size_t stride = (size_t)gridDim.x * blockDim.x;
    for (; i < n4; i += stride) {
        float4 v = ((const float4*)src)[i];
        ((float4*)dst)[i] =
            make_float4(cvt_tf32(v.x), cvt_tf32(v.y), cvt_tf32(v.z), cvt_tf32(v.w));
    }
}

// ---------------- kernel 0: zero expert counters ----------------
__global__ void zero_cnt_kernel() {
    if (threadIdx.x < NEXP) g_cnt[threadIdx.x] = 0;
}

// ---------------- kernel 1: fp32 router ----------------
__global__ void router_kernel(const float* __restrict__ x, const float* __restrict__ gw) {
    __shared__ float sx[H_DIM];
    __shared__ float slog[NEXP];
    const int t = blockIdx.x;
    for (int i = threadIdx.x; i < H_DIM; i += 256) sx[i] = x[(size_t)t * H_DIM + i];
    __syncthreads();
    const int wid = threadIdx.x >> 5, lane = threadIdx.x & 31;
    float s = 0.f;
    const float* w = gw + wid * H_DIM;
    for (int k = lane; k < H_DIM; k += 32) s += sx[k] * w[k];
#pragma unroll
    for (int o = 16; o; o >>= 1) s += __shfl_xor_sync(0xffffffffu, s, o);
    if (lane == 0) slog[wid] = s;
    __syncthreads();
    if (threadIdx.x == 0) {
        float p[NEXP];
        float mx = slog[0];
#pragma unroll
        for (int e = 1; e < NEXP; e++) mx = fmaxf(mx, slog[e]);
        float sum = 0.f;
#pragma unroll
        for (int e = 0; e < NEXP; e++) { p[e] = expf(slog[e] - mx); sum += p[e]; }
        const float inv = 1.f / sum;
#pragma unroll
        for (int e = 0; e < NEXP; e++) p[e] *= inv;
        int i0 = 0;
#pragma unroll
        for (int e = 1; e < NEXP; e++) if (p[e] > p[i0]) i0 = e;
        int i1 = (i0 == 0) ? 1 : 0;
#pragma unroll
        for (int e = 0; e < NEXP; e++) if (e != i1 && e != i0 && p[e] > p[i1]) i1 = e;
        float w0 = p[i0], w1 = p[i1];
        const float rn = 1.f / (w0 + w1 + 1e-20f);
        w0 *= rn; w1 *= rn;
        int p0 = atomicAdd(&g_cnt[i0], 1);
        g_tok [i0 * T_TOKENS + p0] = t;
        g_wgt [i0 * T_TOKENS + p0] = w0;
        g_slot[i0 * T_TOKENS + p0] = 2 * t;
        int p1 = atomicAdd(&g_cnt[i1], 1);
        g_tok [i1 * T_TOKENS + p1] = t;
        g_wgt [i1 * T_TOKENS + p1] = w1;
        g_slot[i1 * T_TOKENS + p1] = 2 * t + 1;
    }
}

// ---------------- kernel 2: fused gate+up GEMM, cp.async + ldmatrix ----------------
// BM=128, BN=64 (two weight mats), BK=32. 2-stage smem pipeline.
#define G1_STAGE 9216   // (128+64+64)*36 floats
__global__ __launch_bounds__(256, 2) void gemm1_kernel() {
    extern __shared__ float smem[];
    const int seg = blockIdx.x >> 6;
    const int mt  = blockIdx.x & 63;
    const int nt  = blockIdx.y;
    const float *wg, *wu;
    if (seg < NEXP) {
        if (mt * 128 >= g_cnt[seg]) return;
        wg = g_egc + (size_t)seg * I_DIM * H_DIM;
        wu = g_euc + (size_t)seg * I_DIM * H_DIM;
    } else { wg = g_sgc; wu = g_suc; }

    const int tid = threadIdx.x;
    const int wid = tid >> 5, lane = tid & 31;
    const int wm = (wid >> 1) * 32, wn = (wid & 1) * 32;
    const int m0 = mt * 128, n0 = nt * 64;
    const int lr = tid >> 3, lc = (tid & 7) * 4;
    const int l7 = lane & 7;
    const int arow = ((lane >> 3) & 1) * 8 + l7, acol = ((lane >> 4) & 1) * 4;
    const int brow = ((lane >> 4) & 1) * 8 + l7, bcol = ((lane >> 3) & 1) * 4;

    int tok[4];
#pragma unroll
    for (int p = 0; p < 4; p++) {
        const int row = m0 + p * 32 + lr;
        tok[p] = (seg == NEXP) ? row : g_tok[seg * T_TOKENS + row];
    }
    const uint32_t sbase = (uint32_t)__cvta_generic_to_shared(smem);

    float accg[2][4][4] = {};
    float accu[2][4][4] = {};

    auto fill = [&](int kk, int s) {
        float* sX = smem + s * G1_STAGE;
        float* sG = sX + 128 * 36;
        float* sU = sG + 64 * 36;
#pragma unroll
        for (int p = 0; p < 4; p++)
            cp16(sX + (p * 32 + lr) * 36 + lc, g_xc + (size_t)tok[p] * H_DIM + kk + lc);
#pragma unroll
        for (int p = 0; p < 2; p++) {
            cp16(sG + (p * 32 + lr) * 36 + lc, wg + (size_t)(n0 + p * 32 + lr) * H_DIM + kk + lc);
            cp16(sU + (p * 32 + lr) * 36 + lc, wu + (size_t)(n0 + p * 32 + lr) * H_DIM + kk + lc);
        }
    };

    const int KT = H_DIM / 32;  // 32
    fill(0, 0);
    cp_commit();
#pragma unroll 1
    for (int kt = 0; kt < KT; ++kt) {
        if (kt + 1 < KT) { fill((kt + 1) * 32, (kt + 1) & 1); cp_commit(); cp_wait<1>(); }
        else cp_wait<0>();
        __syncthreads();
        const uint32_t xb = sbase + (uint32_t)((kt & 1) * G1_STAGE) * 4u;
        const uint32_t gb = xb + 128 * 36 * 4;
        const uint32_t ub = gb + 64 * 36 * 4;
#pragma unroll
        for (int ka = 0; ka < 32; ka += 8) {
            uint32_t a[2][4];
#pragma unroll
            for (int i = 0; i < 2; i++)
                ldsm4(a[i][0], a[i][1], a[i][2], a[i][3],
                      xb + (uint32_t)((wm + i * 16 + arow) * 36 + ka + acol) * 4u);
            uint32_t bg[4][2], bu[4][2];
#pragma unroll
            for (int jj = 0; jj < 2; jj++) {
                uint32_t t0, t1, t2, t3;
                ldsm4(t0, t1, t2, t3,
                      gb + (uint32_t)((wn + jj * 16 + brow) * 36 + ka + bcol) * 4u);
                bg[2 * jj][0] = t0; bg[2 * jj][1] = t1;
                bg[2 * jj + 1][0] = t2; bg[2 * jj + 1][1] = t3;
                ldsm4(t0, t1, t2, t3,
                      ub + (uint32_t)((wn + jj * 16 + brow) * 36 + ka + bcol) * 4u);
                bu[2 * jj][0] = t0; bu[2 * jj][1] = t1;
                bu[2 * jj + 1][0] = t2; bu[2 * jj + 1][1] = t3;
            }
#pragma unroll
            for (int j = 0; j < 4; j++)
#pragma unroll
                for (int i = 0; i < 2; i++) {
                    mma_tf32(accg[i][j], a[i], bg[j]);
                    mma_tf32(accu[i][j], a[i], bu[j]);
                }
        }
        __syncthreads();
    }
    // epilogue: A = silu(g)*u, stored tf32-rounded so gemm2 can cp.async raw
    const int rr = lane >> 2, cc2 = (lane & 3) * 2;
#pragma unroll
    for (int i = 0; i < 2; i++)
#pragma unroll
        for (int j = 0; j < 4; j++)
#pragma unroll
            for (int q = 0; q < 2; q++) {
                const int row = m0 + wm + i * 16 + rr + q * 8;
                const int col = n0 + wn + j * 8 + cc2;
                const float g0 = accg[i][j][q * 2 + 0], g1 = accg[i][j][q * 2 + 1];
                const float u0 = accu[i][j][q * 2 + 0], u1 = accu[i][j][q * 2 + 1];
                const float a0 = cvt_tf32(g0 / (1.f + __expf(-g0)) * u0);
                const float a1 = cvt_tf32(g1 / (1.f + __expf(-g1)) * u1);
                *(float2*)&g_Abuf[((size_t)seg * T_TOKENS + row) * I_DIM + col] =
                    make_float2(a0, a1);
            }
}

// ---------------- kernel 3: down GEMM, cp.async + ldmatrix ----------------
// BM=128, BN=128, BK=32. 2-stage pipeline.
#define G2_STAGE 9216   // (128+128)*36 floats
__global__ __launch_bounds__(256, 2) void gemm2_kernel(float* __restrict__ out) {
    extern __shared__ float smem[];
    const int seg = blockIdx.x >> 6;
    const int mt  = blockIdx.x & 63;
    const int nt  = blockIdx.y;
    int cnt = T_TOKENS;
    const float* wd;
    if (seg < NEXP) {
        cnt = g_cnt[seg];
        if (mt * 128 >= cnt) return;
        wd = g_edc + (size_t)seg * H_DIM * I_DIM;
    } else wd = g_sdc;

    const int tid = threadIdx.x, wid = tid >> 5, lane = tid & 31;
    const int wm = (wid >> 2) * 64, wn = (wid & 3) * 32;
    const int m0 = mt * 128, n0 = nt * 128;
    const int lr = tid >> 3, lc = (tid & 7) * 4;
    const int l7 = lane & 7;
    const int arow = ((lane >> 3) & 1) * 8 + l7, acol = ((lane >> 4) & 1) * 4;
    const int brow = ((lane >> 4) & 1) * 8 + l7, bcol = ((lane >> 3) & 1) * 4;
    const float* Arows = g_Abuf + (size_t)seg * T_TOKENS * I_DIM;
    const uint32_t sbase = (uint32_t)__cvta_generic_to_shared(smem);

    float acc[4][4][4] = {};

    auto fill = [&](int kk, int s) {
        float* sA = smem + s * G2_STAGE;
        float* sW = sA + 128 * 36;
#pragma unroll
        for (int p = 0; p < 4; p++) {
            cp16(sA + (p * 32 + lr) * 36 + lc, Arows + (size_t)(m0 + p * 32 + lr) * I_DIM + kk + lc);
            cp16(sW + (p * 32 + lr) * 36 + lc, wd + (size_t)(n0 + p * 32 + lr) * I_DIM + kk + lc);
        }
    };

    const int KT = I_DIM / 32;  // 88
    fill(0, 0);
    cp_commit();
#pragma unroll 1
    for (int kt = 0; kt < KT; ++kt) {
        if (kt + 1 < KT) { fill((kt + 1) * 32, (kt + 1) & 1); cp_commit(); cp_wait<1>(); }
        else cp_wait<0>();
        __syncthreads();
        const uint32_t ab = sbase + (uint32_t)((kt & 1) * G2_STAGE) * 4u;
        const uint32_t wb = ab + 128 * 36 * 4;
#pragma unroll
        for (int ka = 0; ka < 32; ka += 8) {
            uint32_t a[4][4];
#pragma unroll
            for (int i = 0; i < 4; i++)
                ldsm4(a[i][0], a[i][1], a[i][2], a[i][3],
                      ab + (uint32_t)((wm + i * 16 + arow) * 36 + ka + acol) * 4u);
            uint32_t b[4][2];
#pragma unroll
            for (int jj = 0; jj < 2; jj++) {
                uint32_t t0, t1, t2, t3;
                ldsm4(t0, t1, t2, t3,
                      wb + (uint32_t)((wn + jj * 16 + brow) * 36 + ka + bcol) * 4u);
                b[2 * jj][0] = t0; b[2 * jj][1] = t1;
                b[2 * jj + 1][0] = t2; b[2 * jj + 1][1] = t3;
            }
#pragma unroll
            for (int i = 0; i < 4; i++)
#pragma unroll
                for (int j = 0; j < 4; j++) mma_tf32(acc[i][j], a[i], b[j]);
        }
        __syncthreads();
    }
    const int rr = lane >> 2, cc2 = (lane & 3) * 2;
#pragma unroll
    for (int i = 0; i < 4; i++)
#pragma unroll
        for (int j = 0; j < 4; j++)
#pragma unroll
            for (int q = 0; q < 2; q++) {
                const int row = m0 + wm + i * 16 + rr + q * 8;
                const int col = n0 + wn + j * 8 + cc2;
                const float v0 = acc[i][j][q * 2 + 0], v1 = acc[i][j][q * 2 + 1];
                if (seg == NEXP) {
                    *(float2*)&out[(size_t)row * H_DIM + col] = make_float2(v0, v1);
                } else if (row < cnt) {
                    const int idx  = seg * T_TOKENS + row;
                    const float w  = g_wgt[idx];
                    const int slot = g_slot[idx];
                    *(float2*)&g_Dbuf[(size_t)slot * H_DIM + col] =
                        make_float2(w * v0, w * v1);
                }
            }
}

// ---------------- kernel 4: combine ----------------
__global__ void combine_kernel(float* __restrict__ out) {
    const size_t i = (size_t)blockIdx.x * 256 + threadIdx.x;
    const int t = (int)(i >> 10), h = (int)(i & 1023);
    out[i] += g_Dbuf[(size_t)(2 * t) * H_DIM + h] + g_Dbuf[(size_t)(2 * t + 1) * H_DIM + h];
}

// ---------------- launch ----------------
extern "C" void kernel_launch(void* const* d_in, const int* in_sizes, int n_in,
                              void* d_out, int out_size) {
    const float* x  = (const float*)d_in[0];
    const float* gw = (const float*)d_in[1];
    const float* eg = (const float*)d_in[2];
    const float* eu = (const float*)d_in[3];
    const float* ed = (const float*)d_in[4];
    const float* sg = (const float*)d_in[5];
    const float* su = (const float*)d_in[6];
    const float* sd = (const float*)d_in[7];
    float* out = (float*)d_out;

    cudaFuncSetAttribute(gemm1_kernel, cudaFuncAttributeMaxDynamicSharedMemorySize, 73728);
    cudaFuncSetAttribute(gemm2_kernel, cudaFuncAttributeMaxDynamicSharedMemorySize, 73728);

    const size_t nE = (size_t)NEXP * I_DIM * H_DIM / 4;  // float4 counts
    const size_t nS = (size_t)I_DIM * H_DIM / 4;
    const size_t nX = (size_t)T_TOKENS * H_DIM / 4;
    cvt_kernel<<<1024, 256>>>(x,  0, nX);
    cvt_kernel<<<2048, 256>>>(eg, 1, nE);
    cvt_kernel<<<2048, 256>>>(eu, 2, nE);
    cvt_kernel<<<2048, 256>>>(ed, 3, nE);
    cvt_kernel<<<512,  256>>>(sg, 4, nS);
    cvt_kernel<<<512,  256>>>(su, 5, nS);
    cvt_kernel<<<512,  256>>>(sd, 6, nS);

    zero_cnt_kernel<<<1, 32>>>();
    router_kernel<<<T_TOKENS, 256>>>(x, gw);
    gemm1_kernel<<<dim3(SEGS * 64, I_DIM / 64), 256, 73728>>>();
    gemm2_kernel<<<dim3(SEGS * 64, H_DIM / 128), 256, 73728>>>(out);
    combine_kernel<<<(T_TOKENS * H_DIM) / 256, 256>>>(out);
}